// round 5
// baseline (speedup 1.0000x reference)
#include <cuda_runtime.h>
#include <cstdint>

#define N_NODES 100000
#define N_EDGES 3200000
#define D0 128
#define D1 64
#define D2 32

// -------- persistent scratch (device globals; no allocation allowed) --------
__device__ float g_xw1[N_NODES * D1];   // emb @ W1
__device__ float g_agg1[N_NODES * D1];  // layer-1 aggregate -> h (in place)
__device__ float g_xw2[N_NODES * D2];   // h @ W2
__device__ float g_agg2[N_NODES * D2];  // layer-2 aggregate -> z (in place)
__device__ float g_dis[N_NODES];        // rsqrt(deg+1)
__device__ int   g_deg[N_NODES];
__device__ int   g_src[N_EDGES];        // normalized int32 src
__device__ int   g_dst[N_EDGES];        // normalized int32 dst
__device__ int   g_idx32;               // 1 if edge_index stored as int32

// -------- K_zero: zero all accumulators (no memset API, no symbol lookup) ----
__global__ void k_zero() {
    int i = blockIdx.x * blockDim.x + threadIdx.x;
    if (i < N_NODES * D1) g_agg1[i] = 0.0f;
    if (i < N_NODES * D2) g_agg2[i] = 0.0f;
    if (i < N_NODES)      g_deg[i]  = 0;
}

// -------- K_detect: int32 vs int64 on-disk layout --------
// int64 indices in [0,100000): every qword's high 32 bits are 0.
// int32 layout: qword high half is another random index; over 256 qwords the
// probability all are zero is ~(1e-5)^256 ~ 0.
__global__ void k_detect(const unsigned long long* p) {
    int f = (p[threadIdx.x] >> 32) != 0ull ? 1 : 0;
    int any = __syncthreads_or(f);
    if (threadIdx.x == 0) g_idx32 = any;
}

// -------- K_cvt: normalize edge_index into g_src / g_dst (int32) --------
__global__ void k_cvt(const void* __restrict__ ei, int E) {
    int e = blockIdx.x * blockDim.x + threadIdx.x;
    if (e >= E) return;
    if (g_idx32) {
        const int* p = (const int*)ei;
        g_src[e] = p[e];
        g_dst[e] = p[E + e];
    } else {
        // little-endian int64 with values < 2^31: low word is the value
        const int* p = (const int*)ei;
        g_src[e] = p[2 * e];
        g_dst[e] = p[2 * (E + e)];
    }
}

// -------- K_deg: in-degree counts --------
__global__ void k_deg(int E) {
    int e = blockIdx.x * blockDim.x + threadIdx.x;
    if (e >= E) return;
    atomicAdd(&g_deg[g_dst[e]], 1);
}

// -------- K_dis: dis = rsqrt(deg + 1) --------
__global__ void k_dis(int n) {
    int i = blockIdx.x * blockDim.x + threadIdx.x;
    if (i >= n) return;
    g_dis[i] = rsqrtf((float)g_deg[i] + 1.0f);
}

// -------- K_gemm1: xw1[n,64] = emb[n,128] @ W1[128,64], 1 thread / output ----
__global__ void k_gemm1(const float* __restrict__ emb, const float* __restrict__ W1) {
    __shared__ float Ws[D0 * D1];
    for (int i = threadIdx.x; i < D0 * D1; i += blockDim.x) Ws[i] = W1[i];
    __syncthreads();
    int idx = blockIdx.x * blockDim.x + threadIdx.x;
    if (idx >= N_NODES * D1) return;
    int node = idx / D1, j = idx % D1;
    const float* x = emb + (size_t)node * D0;
    float acc = 0.0f;
    #pragma unroll
    for (int k = 0; k < D0; k++) acc = fmaf(x[k], Ws[k * D1 + j], acc);
    g_xw1[idx] = acc;
}

// -------- scatter: agg[dst, 4q..4q+3] += norm * xw[src, 4q..4q+3] --------
template <int DIMS>
__global__ void k_scatter(int E) {
    const int Q = DIMS / 4;
    long long t = (long long)blockIdx.x * blockDim.x + threadIdx.x;
    int e = (int)(t / Q);
    int q = (int)(t % Q);
    if (e >= E) return;
    int s = g_src[e];
    int d = g_dst[e];
    float norm = g_dis[s] * g_dis[d];
    const float* xw  = (DIMS == D1) ? g_xw1  : g_xw2;
    float*       agg = (DIMS == D1) ? g_agg1 : g_agg2;
    const float* xs = xw + (size_t)s * DIMS + 4 * q;
    float*       ad = agg + (size_t)d * DIMS + 4 * q;
    atomicAdd(ad + 0, xs[0] * norm);
    atomicAdd(ad + 1, xs[1] * norm);
    atomicAdd(ad + 2, xs[2] * norm);
    atomicAdd(ad + 3, xs[3] * norm);
}

// -------- K_fin1: h = relu(agg1 + dis^2 * xw1 + b1)  (in place) --------
__global__ void k_fin1(const float* __restrict__ b1) {
    int i = blockIdx.x * blockDim.x + threadIdx.x;
    if (i >= N_NODES * D1) return;
    int node = i / D1, j = i % D1;
    float dd = g_dis[node]; dd *= dd;
    float v = g_agg1[i] + dd * g_xw1[i] + b1[j];
    g_agg1[i] = v > 0.0f ? v : 0.0f;
}

// -------- K_gemm2: xw2[n,32] = h[n,64] @ W2[64,32], 1 thread / output --------
__global__ void k_gemm2(const float* __restrict__ W2) {
    __shared__ float Ws[D1 * D2];
    for (int i = threadIdx.x; i < D1 * D2; i += blockDim.x) Ws[i] = W2[i];
    __syncthreads();
    int idx = blockIdx.x * blockDim.x + threadIdx.x;
    if (idx >= N_NODES * D2) return;
    int node = idx / D2, j = idx % D2;
    const float* x = g_agg1 + (size_t)node * D1;
    float acc = 0.0f;
    #pragma unroll
    for (int k = 0; k < D1; k++) acc = fmaf(x[k], Ws[k * D2 + j], acc);
    g_xw2[idx] = acc;
}

// -------- K_fin2: z = agg2 + dis^2 * xw2 + b2  (in place) --------
__global__ void k_fin2(const float* __restrict__ b2) {
    int i = blockIdx.x * blockDim.x + threadIdx.x;
    if (i >= N_NODES * D2) return;
    int node = i / D2, j = i % D2;
    float dd = g_dis[node]; dd *= dd;
    g_agg2[i] = g_agg2[i] + dd * g_xw2[i] + b2[j];
}

// -------- K_decode: out[e] = sigmoid(dot(z[src], z[dst])), 1 thread/edge -----
__global__ void k_decode(int E, float* __restrict__ out) {
    int e = blockIdx.x * blockDim.x + threadIdx.x;
    if (e >= E) return;
    const float* zs = g_agg2 + (size_t)g_src[e] * D2;
    const float* zd = g_agg2 + (size_t)g_dst[e] * D2;
    float p = 0.0f;
    #pragma unroll
    for (int j = 0; j < D2; j++) p = fmaf(zs[j], zd[j], p);
    out[e] = 1.0f / (1.0f + __expf(-p));
}

// ============================ launcher ============================
extern "C" void kernel_launch(void* const* d_in, const int* in_sizes, int n_in,
                              void* d_out, int out_size) {
    // Bind by unique element count; fall back to metadata order.
    const float *emb = 0, *W1 = 0, *b1 = 0, *W2 = 0, *b2 = 0;
    const void* ei = 0;
    for (int i = 0; i < n_in; i++) {
        switch (in_sizes[i]) {
            case N_NODES * D0:   emb = (const float*)d_in[i]; break;
            case D0 * D1:        W1  = (const float*)d_in[i]; break;
            case D1:             b1  = (const float*)d_in[i]; break;
            case D1 * D2:        W2  = (const float*)d_in[i]; break;
            case D2:             b2  = (const float*)d_in[i]; break;
            case 2 * N_EDGES:    ei  = d_in[i];               break;
        }
    }
    if (!emb || !W1 || !b1 || !W2 || !b2 || !ei) {
        emb = (const float*)d_in[0]; W1 = (const float*)d_in[1];
        b1  = (const float*)d_in[2]; W2 = (const float*)d_in[3];
        b2  = (const float*)d_in[4]; ei = d_in[5];
    }
    float* out = (float*)d_out;
    const int E = N_EDGES;
    const int B = 256;

    k_zero<<<(N_NODES * D1 + B - 1) / B, B>>>();
    k_detect<<<1, 256>>>((const unsigned long long*)ei);
    k_cvt<<<(E + B - 1) / B, B>>>(ei, E);
    k_deg<<<(E + B - 1) / B, B>>>(E);
    k_dis<<<(N_NODES + B - 1) / B, B>>>(N_NODES);
    k_gemm1<<<(N_NODES * D1 + B - 1) / B, B>>>(emb, W1);
    {
        long long work = (long long)E * (D1 / 4);
        k_scatter<D1><<<(int)((work + B - 1) / B), B>>>(E);
    }
    k_fin1<<<(N_NODES * D1 + B - 1) / B, B>>>(b1);
    k_gemm2<<<(N_NODES * D2 + B - 1) / B, B>>>(W2);
    {
        long long work = (long long)E * (D2 / 4);
        k_scatter<D2><<<(int)((work + B - 1) / B), B>>>(E);
    }
    k_fin2<<<(N_NODES * D2 + B - 1) / B, B>>>(b2);
    k_decode<<<(E + B - 1) / B, B>>>(E, out);
}

// round 12
// speedup vs baseline: 1.2709x; 1.2709x over previous
#include <cuda_runtime.h>
#include <cstdint>

#define N_NODES 100000
#define N_EDGES 3200000
#define D0 128
#define D1 64
#define D2 32

// -------- persistent scratch (no allocation allowed) --------
__device__ float g_xw1[N_NODES * D1];   // emb @ W1
__device__ float g_agg1[N_NODES * D1];  // layer-1 aggregate -> h (in place)
__device__ float g_xw2[N_NODES * D2];   // h @ W2
__device__ float g_agg2[N_NODES * D2];  // layer-2 aggregate -> z (in place)
__device__ float g_dis[N_NODES];        // rsqrt(deg+1)
__device__ int   g_deg[N_NODES];
__device__ int   g_rs [N_NODES + 1];    // CSR row starts
__device__ int   g_cur[N_NODES];        // fill cursors
__device__ int   g_src[N_EDGES];        // normalized int32 src
__device__ int   g_dst[N_EDGES];        // normalized int32 dst
__device__ int2  g_csr[N_EDGES];        // .x = src, .y = float bits of norm
__device__ int   g_idx32;               // 1 if edge_index stored as int32

// -------- K_zero: zero degree counters (in-kernel; no memset API) --------
__global__ void k_zero() {
    int i = blockIdx.x * blockDim.x + threadIdx.x;
    if (i < N_NODES) g_deg[i] = 0;
}

// -------- K_detect: int32 vs int64 on-disk layout (R5-verified) --------
__global__ void k_detect(const unsigned long long* p) {
    int f = (p[threadIdx.x] >> 32) != 0ull ? 1 : 0;
    int any = __syncthreads_or(f);
    if (threadIdx.x == 0) g_idx32 = any;
}

// -------- K_cvt: normalize edge_index into g_src / g_dst (R5-verified) ------
__global__ void k_cvt(const void* __restrict__ ei, int E) {
    int e = blockIdx.x * blockDim.x + threadIdx.x;
    if (e >= E) return;
    if (g_idx32) {
        const int* p = (const int*)ei;
        g_src[e] = p[e];
        g_dst[e] = p[E + e];
    } else {
        // little-endian int64 with values < 2^31: low word is the value
        const int* p = (const int*)ei;
        g_src[e] = p[2 * e];
        g_dst[e] = p[2 * (E + e)];
    }
}

// -------- K_deg: in-degree counts (R5-verified) --------
__global__ void k_deg(int E) {
    int e = blockIdx.x * blockDim.x + threadIdx.x;
    if (e >= E) return;
    atomicAdd(&g_deg[g_dst[e]], 1);
}

// -------- K_dis: dis = rsqrt(deg + 1) (R5-verified) --------
__global__ void k_dis(int n) {
    int i = blockIdx.x * blockDim.x + threadIdx.x;
    if (i >= n) return;
    g_dis[i] = rsqrtf((float)g_deg[i] + 1.0f);
}

// -------- K_scan: exclusive prefix sum of deg -> g_rs, g_cur (1 block) ------
__global__ void k_scan() {
    __shared__ int buf[2][1024];
    int tid = threadIdx.x;
    int carry = 0;
    for (int base = 0; base < N_NODES; base += 1024) {
        int i = base + tid;
        int v = (i < N_NODES) ? g_deg[i] : 0;
        buf[0][tid] = v;
        __syncthreads();
        int pin = 0;
        #pragma unroll
        for (int off = 1; off < 1024; off <<= 1) {
            int t = buf[pin][tid];
            if (tid >= off) t += buf[pin][tid - off];
            buf[pin ^ 1][tid] = t;
            pin ^= 1;
            __syncthreads();
        }
        int incl = buf[pin][tid];
        int excl = incl - v;
        if (i < N_NODES) { g_rs[i] = carry + excl; g_cur[i] = carry + excl; }
        carry += buf[pin][1023];
        __syncthreads();   // protect buf before next chunk overwrites
    }
    if (tid == 0) g_rs[N_NODES] = N_EDGES;   // sum(deg) == E exactly
}

// -------- K_fill: place edges into CSR slots (int atomics on cursors) -------
__global__ void k_fill(int E) {
    int e = blockIdx.x * blockDim.x + threadIdx.x;
    if (e >= E) return;
    int s = g_src[e];
    int d = g_dst[e];
    int pos = atomicAdd(&g_cur[d], 1);
    float nm = g_dis[s] * g_dis[d];
    g_csr[pos] = make_int2(s, __float_as_int(nm));
}

// -------- K_gemm1: xw1[n,64] = emb[n,128] @ W1[128,64] (R5-verified) --------
__global__ void k_gemm1(const float* __restrict__ emb, const float* __restrict__ W1) {
    __shared__ float Ws[D0 * D1];
    for (int i = threadIdx.x; i < D0 * D1; i += blockDim.x) Ws[i] = W1[i];
    __syncthreads();
    int idx = blockIdx.x * blockDim.x + threadIdx.x;
    if (idx >= N_NODES * D1) return;
    int node = idx / D1, j = idx % D1;
    const float* x = emb + (size_t)node * D0;
    float acc = 0.0f;
    #pragma unroll
    for (int k = 0; k < D0; k++) acc = fmaf(x[k], Ws[k * D1 + j], acc);
    g_xw1[idx] = acc;
}

// -------- K_gather1: agg1[node][j] = sum_e norm * xw1[src][j] --------
// One warp per node; lane j owns dims j and j+32. Coalesced 128B row reads.
__global__ void k_gather1() {
    int w = (blockIdx.x * blockDim.x + threadIdx.x) >> 5;
    if (w >= N_NODES) return;
    int lane = threadIdx.x & 31;
    int beg = g_rs[w], end = g_rs[w + 1];
    float a0 = 0.0f, a1 = 0.0f;
    for (int e = beg; e < end; e++) {
        int2 ed = g_csr[e];
        float nm = __int_as_float(ed.y);
        const float* x = g_xw1 + (size_t)ed.x * D1;
        a0 = fmaf(nm, x[lane], a0);
        a1 = fmaf(nm, x[lane + 32], a1);
    }
    g_agg1[(size_t)w * D1 + lane]      = a0;
    g_agg1[(size_t)w * D1 + lane + 32] = a1;
}

// -------- K_fin1: h = relu(agg1 + dis^2 * xw1 + b1) (in place; R5-verified) --
__global__ void k_fin1(const float* __restrict__ b1) {
    int i = blockIdx.x * blockDim.x + threadIdx.x;
    if (i >= N_NODES * D1) return;
    int node = i / D1, j = i % D1;
    float dd = g_dis[node]; dd *= dd;
    float v = g_agg1[i] + dd * g_xw1[i] + b1[j];
    g_agg1[i] = v > 0.0f ? v : 0.0f;
}

// -------- K_gemm2: xw2[n,32] = h[n,64] @ W2[64,32] (R5-verified) --------
__global__ void k_gemm2(const float* __restrict__ W2) {
    __shared__ float Ws[D1 * D2];
    for (int i = threadIdx.x; i < D1 * D2; i += blockDim.x) Ws[i] = W2[i];
    __syncthreads();
    int idx = blockIdx.x * blockDim.x + threadIdx.x;
    if (idx >= N_NODES * D2) return;
    int node = idx / D2, j = idx % D2;
    const float* x = g_agg1 + (size_t)node * D1;
    float acc = 0.0f;
    #pragma unroll
    for (int k = 0; k < D1; k++) acc = fmaf(x[k], Ws[k * D2 + j], acc);
    g_xw2[idx] = acc;
}

// -------- K_gather2: agg2[node][j] = sum_e norm * xw2[src][j] --------
__global__ void k_gather2() {
    int w = (blockIdx.x * blockDim.x + threadIdx.x) >> 5;
    if (w >= N_NODES) return;
    int lane = threadIdx.x & 31;
    int beg = g_rs[w], end = g_rs[w + 1];
    float a0 = 0.0f;
    for (int e = beg; e < end; e++) {
        int2 ed = g_csr[e];
        a0 = fmaf(__int_as_float(ed.y), g_xw2[(size_t)ed.x * D2 + lane], a0);
    }
    g_agg2[(size_t)w * D2 + lane] = a0;
}

// -------- K_fin2: z = agg2 + dis^2 * xw2 + b2 (in place; R5-verified) --------
__global__ void k_fin2(const float* __restrict__ b2) {
    int i = blockIdx.x * blockDim.x + threadIdx.x;
    if (i >= N_NODES * D2) return;
    int node = i / D2, j = i % D2;
    float dd = g_dis[node]; dd *= dd;
    g_agg2[i] = g_agg2[i] + dd * g_xw2[i] + b2[j];
}

// -------- K_decode: out[e] = sigmoid(dot(z[src], z[dst])) (R5-verified) ------
__global__ void k_decode(int E, float* __restrict__ out) {
    int e = blockIdx.x * blockDim.x + threadIdx.x;
    if (e >= E) return;
    const float* zs = g_agg2 + (size_t)g_src[e] * D2;
    const float* zd = g_agg2 + (size_t)g_dst[e] * D2;
    float p = 0.0f;
    #pragma unroll
    for (int j = 0; j < D2; j++) p = fmaf(zs[j], zd[j], p);
    out[e] = 1.0f / (1.0f + __expf(-p));
}

// ============================ launcher ============================
extern "C" void kernel_launch(void* const* d_in, const int* in_sizes, int n_in,
                              void* d_out, int out_size) {
    const float *emb = 0, *W1 = 0, *b1 = 0, *W2 = 0, *b2 = 0;
    const void* ei = 0;
    for (int i = 0; i < n_in; i++) {
        switch (in_sizes[i]) {
            case N_NODES * D0:   emb = (const float*)d_in[i]; break;
            case D0 * D1:        W1  = (const float*)d_in[i]; break;
            case D1:             b1  = (const float*)d_in[i]; break;
            case D1 * D2:        W2  = (const float*)d_in[i]; break;
            case D2:             b2  = (const float*)d_in[i]; break;
            case 2 * N_EDGES:    ei  = d_in[i];               break;
        }
    }
    if (!emb || !W1 || !b1 || !W2 || !b2 || !ei) {
        emb = (const float*)d_in[0]; W1 = (const float*)d_in[1];
        b1  = (const float*)d_in[2]; W2 = (const float*)d_in[3];
        b2  = (const float*)d_in[4]; ei = d_in[5];
    }
    float* out = (float*)d_out;
    const int E = N_EDGES;
    const int B = 256;

    // ---- graph preprocessing: degrees + CSR ----
    k_zero<<<(N_NODES + B - 1) / B, B>>>();
    k_detect<<<1, 256>>>((const unsigned long long*)ei);
    k_cvt<<<(E + B - 1) / B, B>>>(ei, E);
    k_deg<<<(E + B - 1) / B, B>>>(E);
    k_dis<<<(N_NODES + B - 1) / B, B>>>(N_NODES);
    k_scan<<<1, 1024>>>();
    k_fill<<<(E + B - 1) / B, B>>>(E);

    // ---- layer 1 ----
    k_gemm1<<<(N_NODES * D1 + B - 1) / B, B>>>(emb, W1);
    k_gather1<<<(N_NODES * 32 + B - 1) / B, B>>>();
    k_fin1<<<(N_NODES * D1 + B - 1) / B, B>>>(b1);

    // ---- layer 2 ----
    k_gemm2<<<(N_NODES * D2 + B - 1) / B, B>>>(W2);
    k_gather2<<<(N_NODES * 32 + B - 1) / B, B>>>();
    k_fin2<<<(N_NODES * D2 + B - 1) / B, B>>>(b2);

    // ---- decode ----
    k_decode<<<(E + B - 1) / B, B>>>(E, out);
}

// round 17
// speedup vs baseline: 2.5823x; 2.0319x over previous
#include <cuda_runtime.h>
#include <cstdint>

#define N_NODES 100000
#define N_EDGES 3200000
#define D0 128
#define D1 64
#define D2 32
#define NCHUNK ((N_NODES + 1023) / 1024)   // 98

// -------- persistent scratch (no allocation allowed; 16B aligned) --------
__device__ __align__(16) float g_xw1[N_NODES * D1];   // emb @ W1
__device__ __align__(16) float g_agg1[N_NODES * D1];  // layer-1 aggregate -> h (in place)
__device__ __align__(16) float g_xw2[N_NODES * D2];   // h @ W2
__device__ __align__(16) float g_agg2[N_NODES * D2];  // layer-2 aggregate -> z (in place)
__device__ float g_dis[N_NODES];        // rsqrt(deg+1)
__device__ int   g_deg[N_NODES];
__device__ int   g_rs [N_NODES + 1];    // CSR row starts
__device__ int   g_cur[N_NODES];        // fill cursors
__device__ int   g_bsum[128];           // per-chunk sums (NCHUNK used)
__device__ int   g_boff[128];           // per-chunk exclusive offsets
__device__ int   g_src[N_EDGES];        // normalized int32 src
__device__ int   g_dst[N_EDGES];        // normalized int32 dst
__device__ int2  g_csr[N_EDGES];        // .x = src, .y = float bits of norm
__device__ int   g_idx32;               // 1 if edge_index stored as int32

// -------- K_zero: zero degree counters (in-kernel; no memset API) --------
__global__ void k_zero() {
    int i = blockIdx.x * blockDim.x + threadIdx.x;
    if (i < N_NODES) g_deg[i] = 0;
}

// -------- K_detect: int32 vs int64 on-disk layout (R5/R12-verified) --------
__global__ void k_detect(const unsigned long long* p) {
    int f = (p[threadIdx.x] >> 32) != 0ull ? 1 : 0;
    int any = __syncthreads_or(f);
    if (threadIdx.x == 0) g_idx32 = any;
}

// -------- K_cvt: normalize edge_index into g_src / g_dst (R12-verified) -----
__global__ void k_cvt(const void* __restrict__ ei, int E) {
    int e = blockIdx.x * blockDim.x + threadIdx.x;
    if (e >= E) return;
    if (g_idx32) {
        const int* p = (const int*)ei;
        g_src[e] = p[e];
        g_dst[e] = p[E + e];
    } else {
        // little-endian int64 with values < 2^31: low word is the value
        const int* p = (const int*)ei;
        g_src[e] = p[2 * e];
        g_dst[e] = p[2 * (E + e)];
    }
}

// -------- K_deg: in-degree counts (R12-verified) --------
__global__ void k_deg(int E) {
    int e = blockIdx.x * blockDim.x + threadIdx.x;
    if (e >= E) return;
    atomicAdd(&g_deg[g_dst[e]], 1);
}

// -------- K_dis: dis = rsqrt(deg + 1) (R12-verified) --------
__global__ void k_dis(int n) {
    int i = blockIdx.x * blockDim.x + threadIdx.x;
    if (i >= n) return;
    g_dis[i] = rsqrtf((float)g_deg[i] + 1.0f);
}

// -------- K_scan_local: per-chunk exclusive scan of deg (98 blocks) --------
// Same Hillis-Steele inner loop as the R12-verified single-block scan.
__global__ void k_scan_local() {
    __shared__ int buf[2][1024];
    int tid = threadIdx.x;
    int i = blockIdx.x * 1024 + tid;
    int v = (i < N_NODES) ? g_deg[i] : 0;
    buf[0][tid] = v;
    __syncthreads();
    int pin = 0;
    #pragma unroll
    for (int off = 1; off < 1024; off <<= 1) {
        int t = buf[pin][tid];
        if (tid >= off) t += buf[pin][tid - off];
        buf[pin ^ 1][tid] = t;
        pin ^= 1;
        __syncthreads();
    }
    int incl = buf[pin][tid];
    if (i < N_NODES) g_rs[i] = incl - v;               // local exclusive
    if (tid == 1023) g_bsum[blockIdx.x] = incl;        // chunk total
}

// -------- K_scan_chunks: exclusive scan of 98 chunk sums (1 block, 128 thr) --
__global__ void k_scan_chunks() {
    __shared__ int buf[2][128];
    int tid = threadIdx.x;
    int v = (tid < NCHUNK) ? g_bsum[tid] : 0;
    buf[0][tid] = v;
    __syncthreads();
    int pin = 0;
    #pragma unroll
    for (int off = 1; off < 128; off <<= 1) {
        int t = buf[pin][tid];
        if (tid >= off) t += buf[pin][tid - off];
        buf[pin ^ 1][tid] = t;
        pin ^= 1;
        __syncthreads();
    }
    int incl = buf[pin][tid];
    if (tid < NCHUNK) g_boff[tid] = incl - v;          // exclusive chunk offset
}

// -------- K_scan_add: g_rs += chunk offset; init cursors --------
__global__ void k_scan_add() {
    int i = blockIdx.x * blockDim.x + threadIdx.x;
    if (i >= N_NODES) return;
    int r = g_rs[i] + g_boff[i >> 10];
    g_rs[i] = r;
    g_cur[i] = r;
    if (i == 0) g_rs[N_NODES] = N_EDGES;   // sum(deg) == E exactly
}

// -------- K_fill: place edges into CSR slots (int atomics; R12-verified) ----
__global__ void k_fill(int E) {
    int e = blockIdx.x * blockDim.x + threadIdx.x;
    if (e >= E) return;
    int s = g_src[e];
    int d = g_dst[e];
    int pos = atomicAdd(&g_cur[d], 1);
    float nm = g_dis[s] * g_dis[d];
    g_csr[pos] = make_int2(s, __float_as_int(nm));
}

// -------- K_gemm1: xw1[n,64] = emb[n,128] @ W1[128,64] (R12-verified) -------
__global__ void k_gemm1(const float* __restrict__ emb, const float* __restrict__ W1) {
    __shared__ float Ws[D0 * D1];
    for (int i = threadIdx.x; i < D0 * D1; i += blockDim.x) Ws[i] = W1[i];
    __syncthreads();
    int idx = blockIdx.x * blockDim.x + threadIdx.x;
    if (idx >= N_NODES * D1) return;
    int node = idx / D1, j = idx % D1;
    const float* x = emb + (size_t)node * D0;
    float acc = 0.0f;
    #pragma unroll
    for (int k = 0; k < D0; k++) acc = fmaf(x[k], Ws[k * D1 + j], acc);
    g_xw1[idx] = acc;
}

// -------- K_gather1: agg1[node][j] = sum_e norm * xw1[src][j] (R12-verified) -
__global__ void k_gather1() {
    int w = (blockIdx.x * blockDim.x + threadIdx.x) >> 5;
    if (w >= N_NODES) return;
    int lane = threadIdx.x & 31;
    int beg = g_rs[w], end = g_rs[w + 1];
    float a0 = 0.0f, a1 = 0.0f;
    for (int e = beg; e < end; e++) {
        int2 ed = g_csr[e];
        float nm = __int_as_float(ed.y);
        const float* x = g_xw1 + (size_t)ed.x * D1;
        a0 = fmaf(nm, x[lane], a0);
        a1 = fmaf(nm, x[lane + 32], a1);
    }
    g_agg1[(size_t)w * D1 + lane]      = a0;
    g_agg1[(size_t)w * D1 + lane + 32] = a1;
}

// -------- K_fin1: h = relu(agg1 + dis^2 * xw1 + b1) (R12-verified) --------
__global__ void k_fin1(const float* __restrict__ b1) {
    int i = blockIdx.x * blockDim.x + threadIdx.x;
    if (i >= N_NODES * D1) return;
    int node = i / D1, j = i % D1;
    float dd = g_dis[node]; dd *= dd;
    float v = g_agg1[i] + dd * g_xw1[i] + b1[j];
    g_agg1[i] = v > 0.0f ? v : 0.0f;
}

// -------- K_gemm2: xw2[n,32] = h[n,64] @ W2[64,32] (R12-verified) --------
__global__ void k_gemm2(const float* __restrict__ W2) {
    __shared__ float Ws[D1 * D2];
    for (int i = threadIdx.x; i < D1 * D2; i += blockDim.x) Ws[i] = W2[i];
    __syncthreads();
    int idx = blockIdx.x * blockDim.x + threadIdx.x;
    if (idx >= N_NODES * D2) return;
    int node = idx / D2, j = idx % D2;
    const float* x = g_agg1 + (size_t)node * D1;
    float acc = 0.0f;
    #pragma unroll
    for (int k = 0; k < D1; k++) acc = fmaf(x[k], Ws[k * D2 + j], acc);
    g_xw2[idx] = acc;
}

// -------- K_gather2: agg2[node][j] = sum_e norm * xw2[src][j] (R12-verified) -
__global__ void k_gather2() {
    int w = (blockIdx.x * blockDim.x + threadIdx.x) >> 5;
    if (w >= N_NODES) return;
    int lane = threadIdx.x & 31;
    int beg = g_rs[w], end = g_rs[w + 1];
    float a0 = 0.0f;
    for (int e = beg; e < end; e++) {
        int2 ed = g_csr[e];
        a0 = fmaf(__int_as_float(ed.y), g_xw2[(size_t)ed.x * D2 + lane], a0);
    }
    g_agg2[(size_t)w * D2 + lane] = a0;
}

// -------- K_fin2: z = agg2 + dis^2 * xw2 + b2 (R12-verified) --------
__global__ void k_fin2(const float* __restrict__ b2) {
    int i = blockIdx.x * blockDim.x + threadIdx.x;
    if (i >= N_NODES * D2) return;
    int node = i / D2, j = i % D2;
    float dd = g_dis[node]; dd *= dd;
    g_agg2[i] = g_agg2[i] + dd * g_xw2[i] + b2[j];
}

// -------- K_decode: out[e] = sigmoid(dot(z[src], z[dst])) --------
// 8 lanes per edge; each lane loads one float4 quad of each z row (rows are
// single 128B lines -> ~2 wavefronts/edge vs 64 for the scalar version).
// E*8 = 25.6M is an exact multiple of blockDim=256: no partial warps.
__global__ void k_decode8(int E, float* __restrict__ out) {
    int t = blockIdx.x * blockDim.x + threadIdx.x;
    int e = t >> 3;
    if (e >= E) return;
    int sub = threadIdx.x & 7;
    int s = g_src[e];
    int d = g_dst[e];
    float4 a = ((const float4*)(g_agg2 + (size_t)s * D2))[sub];
    float4 b = ((const float4*)(g_agg2 + (size_t)d * D2))[sub];
    float p = a.x * b.x;
    p = fmaf(a.y, b.y, p);
    p = fmaf(a.z, b.z, p);
    p = fmaf(a.w, b.w, p);
    p += __shfl_xor_sync(0xffffffffu, p, 1);
    p += __shfl_xor_sync(0xffffffffu, p, 2);
    p += __shfl_xor_sync(0xffffffffu, p, 4);
    if (sub == 0) out[e] = 1.0f / (1.0f + __expf(-p));
}

// ============================ launcher ============================
extern "C" void kernel_launch(void* const* d_in, const int* in_sizes, int n_in,
                              void* d_out, int out_size) {
    const float *emb = 0, *W1 = 0, *b1 = 0, *W2 = 0, *b2 = 0;
    const void* ei = 0;
    for (int i = 0; i < n_in; i++) {
        switch (in_sizes[i]) {
            case N_NODES * D0:   emb = (const float*)d_in[i]; break;
            case D0 * D1:        W1  = (const float*)d_in[i]; break;
            case D1:             b1  = (const float*)d_in[i]; break;
            case D1 * D2:        W2  = (const float*)d_in[i]; break;
            case D2:             b2  = (const float*)d_in[i]; break;
            case 2 * N_EDGES:    ei  = d_in[i];               break;
        }
    }
    if (!emb || !W1 || !b1 || !W2 || !b2 || !ei) {
        emb = (const float*)d_in[0]; W1 = (const float*)d_in[1];
        b1  = (const float*)d_in[2]; W2 = (const float*)d_in[3];
        b2  = (const float*)d_in[4]; ei = d_in[5];
    }
    float* out = (float*)d_out;
    const int E = N_EDGES;
    const int B = 256;

    // ---- graph preprocessing: degrees + CSR ----
    k_zero<<<(N_NODES + B - 1) / B, B>>>();
    k_detect<<<1, 256>>>((const unsigned long long*)ei);
    k_cvt<<<(E + B - 1) / B, B>>>(ei, E);
    k_deg<<<(E + B - 1) / B, B>>>(E);
    k_dis<<<(N_NODES + B - 1) / B, B>>>(N_NODES);
    k_scan_local<<<NCHUNK, 1024>>>();
    k_scan_chunks<<<1, 128>>>();
    k_scan_add<<<(N_NODES + B - 1) / B, B>>>();
    k_fill<<<(E + B - 1) / B, B>>>(E);

    // ---- layer 1 ----
    k_gemm1<<<(N_NODES * D1 + B - 1) / B, B>>>(emb, W1);
    k_gather1<<<(N_NODES * 32 + B - 1) / B, B>>>();
    k_fin1<<<(N_NODES * D1 + B - 1) / B, B>>>(b1);

    // ---- layer 2 ----
    k_gemm2<<<(N_NODES * D2 + B - 1) / B, B>>>(W2);
    k_gather2<<<(N_NODES * 32 + B - 1) / B, B>>>();
    k_fin2<<<(N_NODES * D2 + B - 1) / B, B>>>(b2);

    // ---- decode: 8 lanes per edge ----
    {
        long long work = (long long)E * 8;
        k_decode8<<<(int)((work + B - 1) / B), B>>>(E, out);
    }
}